// round 16
// baseline (speedup 1.0000x reference)
#include <cuda_runtime.h>
#include <cuda_fp16.h>
#include <math.h>
#include <stdint.h>

#define DD    1024
#define MB    16384
#define CHUNK 64
// gemm1p tile: CTA 128x128, 8 warps of 32x64 (R8 config: proven optimum)
#define BM    128
#define BN    128
#define BK    64
#define NKC   (DD / BK)        // 16
#define STAGE_B 32768u         // Ah 16K | Wh 16K
#define NSTG  3
#define SMEM_BYTES (NSTG * STAGE_B)
// gemm2w (combine, 2-pass) tile: 128x128, 2-stage, 2 CTAs/SM
#define STAGE2W_B 49152u       // Ah 16K | Al 16K | Wh 16K
#define SMEM2W_BYTES (2u * STAGE2W_B)

// ---------------- scratch (static device arrays; no allocation) ----------------
__device__ __half g_xh[MB * DD];
__device__ __half g_lnh[MB * DD];
__device__ __half g_valh[MB * DD];
__device__ float  g_kp [MB * DD], g_qp[MB * DD];
__device__ __half g_wv_h[DD * DD], g_wo_h[DD * DD];
__device__ __half g_wkp_h[DD * DD], g_wkp_l[DD * DD];
__device__ __half g_wqp_h[DD * DD], g_wqp_l[DD * DD];
__device__ __half g_wkt_h[DD * DD];
__device__ __half g_wqt_h[DD * DD];
__device__ __half g_wck_h[DD * DD], g_wcq_h[DD * DD];
__device__ float  g_bck[DD], g_bcq[DD];

// ---------------- helpers ----------------
__device__ __forceinline__ uint32_t smem_u32(const void* p) {
    uint32_t a;
    asm("{ .reg .u64 t; cvta.to.shared.u64 t, %1; cvt.u32.u64 %0, t; }" : "=r"(a) : "l"(p));
    return a;
}
__device__ __forceinline__ void cp_async16(uint32_t dst, const void* src) {
    asm volatile("cp.async.cg.shared.global [%0], [%1], 16;" :: "r"(dst), "l"(src));
}
__device__ __forceinline__ void cp_commit() {
    asm volatile("cp.async.commit_group;" ::: "memory");
}
template<int N>
__device__ __forceinline__ void cp_wait() {
    asm volatile("cp.async.wait_group %0;" :: "n"(N) : "memory");
}
__device__ __forceinline__ void ldsm4(uint32_t* r, uint32_t addr) {
    asm volatile("ldmatrix.sync.aligned.m8n8.x4.shared.b16 {%0,%1,%2,%3}, [%4];"
                 : "=r"(r[0]), "=r"(r[1]), "=r"(r[2]), "=r"(r[3]) : "r"(addr));
}
__device__ __forceinline__ void mma16816(float* c, const uint32_t* a, uint32_t b0, uint32_t b1) {
    asm volatile(
        "mma.sync.aligned.m16n8k16.row.col.f32.f16.f16.f32 "
        "{%0,%1,%2,%3}, {%4,%5,%6,%7}, {%8,%9}, {%0,%1,%2,%3};"
        : "+f"(c[0]), "+f"(c[1]), "+f"(c[2]), "+f"(c[3])
        : "r"(a[0]), "r"(a[1]), "r"(a[2]), "r"(a[3]), "r"(b0), "r"(b1));
}
__device__ __forceinline__ void split2(float v0, float v1, uint32_t& h, uint32_t& l) {
    __half2 hh = __floats2half2_rn(v0, v1);
    float2 f = __half22float2(hh);
    __half2 ll = __floats2half2_rn(v0 - f.x, v1 - f.y);
    h = *(uint32_t*)&hh; l = *(uint32_t*)&ll;
}

// ---------------- fp32 -> (hi fp16 [, lo fp16]) split, 3 matrices per launch ---
__global__ void __launch_bounds__(256)
split3(const float* __restrict__ s0, const float* __restrict__ s1, const float* __restrict__ s2,
       __half* h0, __half* l0, __half* h1, __half* l1, __half* h2, __half* l2)
{
    const int z = blockIdx.y;
    const float* s = (z == 0) ? s0 : (z == 1) ? s1 : s2;
    __half* h = (z == 0) ? h0 : (z == 1) ? h1 : h2;
    __half* l = (z == 0) ? l0 : (z == 1) ? l1 : l2;
    const size_t i = ((size_t)blockIdx.x * 256 + threadIdx.x) * 4;
    const float4 v = *(const float4*)(s + i);
    uint32_t ha, la, hb, lb;
    split2(v.x, v.y, ha, la);
    split2(v.z, v.w, hb, lb);
    *(uint2*)(h + i) = make_uint2(ha, hb);
    if (l) *(uint2*)(l + i) = make_uint2(la, lb);
}

// ---------------- transpose (hi fp16 only): out[d][m] = in[m][d] ---------------
__global__ void __launch_bounds__(256)
tsplit(const float* __restrict__ s0, const float* __restrict__ s1,
       __half* h0, __half* h1)
{
    __shared__ float t[32][33];
    const int z = blockIdx.z;
    const float* s = z ? s1 : s0;
    __half* h = z ? h1 : h0;
    const int bx = blockIdx.x * 32, by = blockIdx.y * 32;
    const int tx = threadIdx.x & 31, ty = threadIdx.x >> 5;
#pragma unroll
    for (int i = 0; i < 32; i += 8)
        t[ty + i][tx] = s[(size_t)(by + ty + i) * DD + bx + tx];
    __syncthreads();
#pragma unroll
    for (int i = 0; i < 32; i += 8) {
        const float v = t[tx][ty + i];
        h[(size_t)(bx + ty + i) * DD + by + tx] = __float2half_rn(v);
    }
}

// ---------------- bias combine: o[e] = a[e] + sum_m W[e,m] * v[m] --------------
__global__ void __launch_bounds__(256)
matvec(const float* __restrict__ W0, const float* __restrict__ v0, const float* __restrict__ a0,
       const float* __restrict__ W1, const float* __restrict__ v1, const float* __restrict__ a1,
       float* o0, float* o1)
{
    const int z = blockIdx.y;
    const float* W = z ? W1 : W0;
    const float* v = z ? v1 : v0;
    const float* a = z ? a1 : a0;
    float* o = z ? o1 : o0;
    const int e = blockIdx.x, t = threadIdx.x;
    float s = 0.f;
    for (int m = t; m < DD; m += 256)
        s += W[(size_t)e * DD + m] * v[m];
    __shared__ float r[8];
#pragma unroll
    for (int off = 16; off; off >>= 1) s += __shfl_xor_sync(0xffffffffu, s, off);
    if ((t & 31) == 0) r[t >> 5] = s;
    __syncthreads();
    if (t == 0) {
        float tot = a[e];
#pragma unroll
        for (int w = 0; w < 8; w++) tot += r[w];
        o[e] = tot;
    }
}

// ------- 2-pass combine GEMM: Wc[128,128] tile = (Ah+Al) @ Wh^T -> hi fp16 -----
struct CombArgs {
    const __half* Ah[2]; const __half* Al[2];
    const __half* Wh[2];
    __half* Ch[2];
};
__global__ void __launch_bounds__(256, 2)
gemm2w(CombArgs ga)
{
    extern __shared__ char smem[];
    const int tid = threadIdx.x;
    const int z = blockIdx.z;
    const __half* Ahg = ga.Ah[z];
    const __half* Alg = ga.Al[z];
    const __half* Whg = ga.Wh[z];

    const int bm = blockIdx.y * 128;
    const int bn = blockIdx.x * 128;
    const uint32_t sbu = smem_u32(smem);

    auto issue = [&](int kt, int s) {
        const uint32_t st = sbu + (uint32_t)s * STAGE2W_B;
        const int kof = kt * BK;
#pragma unroll
        for (int i = 0; i < 4; i++) {
            const int idx = tid + (i << 8);
            const int row = idx >> 3, c = idx & 7;
            const uint32_t so = st + (uint32_t)row * 128u
                              + (((uint32_t)c * 16u) ^ (((uint32_t)row & 7u) << 4));
            const size_t gA = (size_t)(bm + row) * DD + kof + c * 8;
            cp_async16(so,          Ahg + gA);
            cp_async16(so + 16384u, Alg + gA);
            cp_async16(so + 32768u, Whg + (size_t)(bn + row) * DD + kof + c * 8);
        }
    };

    const int warp = tid >> 5, lane = tid & 31;
    const int wm0 = (warp >> 1) * 32;
    const int wn0 = (warp & 1) * 64;
    const int lr = lane & 15;
    const uint32_t lc   = ((uint32_t)lane >> 4) * 16u;
    const uint32_t xorv = ((uint32_t)lane & 7u) << 4;

    float acc[2][8][4];
#pragma unroll
    for (int mi = 0; mi < 2; mi++)
#pragma unroll
        for (int ni = 0; ni < 8; ni++)
#pragma unroll
            for (int q = 0; q < 4; q++) acc[mi][ni][q] = 0.f;

    auto compute = [&](int s) {
        const uint32_t sA = sbu + (uint32_t)s * STAGE2W_B;
        const uint32_t sW = sA + 32768u;
#pragma unroll
        for (int kk = 0; kk < 4; kk++) {
            const uint32_t koff = (((uint32_t)kk * 32u) + lc) ^ xorv;
            uint32_t ah[2][4], al[2][4], wh[4][4];
#pragma unroll
            for (int mi = 0; mi < 2; mi++) {
                const uint32_t rb = (uint32_t)((wm0 + mi * 16 + lr) * 128) + koff;
                ldsm4(ah[mi], sA + rb);
                ldsm4(al[mi], sA + 16384u + rb);
            }
#pragma unroll
            for (int g = 0; g < 4; g++)
                ldsm4(wh[g], sW + (uint32_t)((wn0 + g * 16 + lr) * 128) + koff);
#pragma unroll
            for (int mi = 0; mi < 2; mi++)
#pragma unroll
                for (int ni = 0; ni < 8; ni++) {
                    const uint32_t* b = wh[ni >> 1];
                    mma16816(acc[mi][ni], ah[mi], b[ni & 1], b[(ni & 1) + 2]);
                }
#pragma unroll
            for (int mi = 0; mi < 2; mi++)
#pragma unroll
                for (int ni = 0; ni < 8; ni++) {
                    const uint32_t* b = wh[ni >> 1];
                    mma16816(acc[mi][ni], al[mi], b[ni & 1], b[(ni & 1) + 2]);
                }
        }
    };

    issue(0, 0); cp_commit();
    issue(1, 1); cp_commit();
    cp_wait<1>();
    __syncthreads();
#pragma unroll 1
    for (int kt = 0; kt < NKC; kt++) {
        compute(kt & 1);
        __syncthreads();
        if (kt + 2 < NKC) issue(kt + 2, kt & 1);
        cp_commit();
        cp_wait<1>();
        __syncthreads();
    }

    __half* Ch = ga.Ch[z];
#pragma unroll
    for (int ni = 0; ni < 8; ni++) {
        const int c = bn + wn0 + ni * 8 + (lane & 3) * 2;
#pragma unroll
        for (int mi = 0; mi < 2; mi++) {
#pragma unroll
            for (int hf = 0; hf < 2; hf++) {
                const int row = bm + wm0 + mi * 16 + (lane >> 2) + hf * 8;
                __half2 hv = __floats2half2_rn(acc[mi][ni][hf * 2], acc[mi][ni][hf * 2 + 1]);
                *(__half2*)(Ch + (size_t)row * DD + c) = hv;
            }
        }
    }
}

// ---------------- GEMM args (runtime per-slice epilogue mode) ------------------
struct GemmArgs {
    const __half* Ah[3];
    const __half* Wh[3];
    const float*  bias[3];
    const float*  extra[3];         // mode1: phase_scale ; mode2: residual x
    float*  Cf[3];                  // fp32 output (or null)
    __half* Ch[3];                  // fp16 output (or null)
    int mode[3];
    int nz;                         // number of z slices folded into grid.x
};

// ------- 1-pass mma GEMM (R8 config): C[128,128], 8 warps 32x64, 3-stage -------
__global__ void __launch_bounds__(256, 2)
gemm1p(GemmArgs ga)
{
    extern __shared__ char smem[];
    const int tid = threadIdx.x;
    const int z  = blockIdx.x % ga.nz;
    const int bn = (blockIdx.x / ga.nz) * BN;
    const __half* Ahg = ga.Ah[z];
    const __half* Whg = ga.Wh[z];
    const float*  bias = ga.bias[z];

    const int bm = blockIdx.y * BM;
    const uint32_t sbu = smem_u32(smem);

    auto issue = [&](int kt, int s) {
        const uint32_t st = sbu + (uint32_t)s * STAGE_B;
        const int kof = kt * BK;
#pragma unroll
        for (int i = 0; i < 4; i++) {
            const int idx = tid + (i << 8);
            const int row = idx >> 3, c = idx & 7;
            const uint32_t so = st + (uint32_t)row * 128u
                              + (((uint32_t)c * 16u) ^ (((uint32_t)row & 7u) << 4));
            cp_async16(so,          Ahg + (size_t)(bm + row) * DD + kof + c * 8);
            cp_async16(so + 16384u, Whg + (size_t)(bn + row) * DD + kof + c * 8);
        }
    };

    const int warp = tid >> 5, lane = tid & 31;
    const int wm0 = (warp >> 1) * 32;
    const int wn0 = (warp & 1) * 64;
    const int lr = lane & 15;
    const uint32_t lc   = ((uint32_t)lane >> 4) * 16u;
    const uint32_t xorv = ((uint32_t)lane & 7u) << 4;

    float acc[2][8][4];
#pragma unroll
    for (int mi = 0; mi < 2; mi++)
#pragma unroll
        for (int ni = 0; ni < 8; ni++)
#pragma unroll
            for (int q = 0; q < 4; q++) acc[mi][ni][q] = 0.f;

    auto compute = [&](int s) {
        const uint32_t sA = sbu + (uint32_t)s * STAGE_B;
        const uint32_t sW = sA + 16384u;
#pragma unroll
        for (int kk = 0; kk < 4; kk++) {
            const uint32_t koff = (((uint32_t)kk * 32u) + lc) ^ xorv;
            uint32_t ah[2][4], wh[4][4];
#pragma unroll
            for (int mi = 0; mi < 2; mi++)
                ldsm4(ah[mi], sA + (uint32_t)((wm0 + mi * 16 + lr) * 128) + koff);
#pragma unroll
            for (int g = 0; g < 4; g++)
                ldsm4(wh[g], sW + (uint32_t)((wn0 + g * 16 + lr) * 128) + koff);
#pragma unroll
            for (int mi = 0; mi < 2; mi++)
#pragma unroll
                for (int ni = 0; ni < 8; ni++) {
                    const uint32_t* b = wh[ni >> 1];
                    mma16816(acc[mi][ni], ah[mi], b[ni & 1], b[(ni & 1) + 2]);
                }
        }
    };

    issue(0, 0); cp_commit();
    issue(1, 1); cp_commit();
#pragma unroll 1
    for (int kt = 0; kt < NKC; kt++) {
        cp_wait<1>();
        __syncthreads();
        if (kt + 2 < NKC) issue(kt + 2, (kt + 2) % NSTG);
        cp_commit();
        compute(kt % NSTG);
    }

    // ---- epilogue ----
    const int mode = ga.mode[z];
    const float* extra = ga.extra[z];
    float*  Cf = ga.Cf[z];
    __half* Ch = ga.Ch[z];

#pragma unroll
    for (int ni = 0; ni < 8; ni++) {
        const int c = bn + wn0 + ni * 8 + (lane & 3) * 2;
        const float b0 = bias[c], b1 = bias[c + 1];
        float p0 = 0.f, p1 = 0.f;
        if (mode == 1) { p0 = extra[c]; p1 = extra[c + 1]; }
#pragma unroll
        for (int mi = 0; mi < 2; mi++) {
#pragma unroll
            for (int hf = 0; hf < 2; hf++) {
                const int row = bm + wm0 + mi * 16 + (lane >> 2) + hf * 8;
                float v0 = acc[mi][ni][hf * 2 + 0] + b0;
                float v1 = acc[mi][ni][hf * 2 + 1] + b1;
                if (mode == 1) { v0 = tanhf(v0) * p0; v1 = tanhf(v1) * p1; }
                if (mode == 2) {
                    const float2 rr = *(const float2*)(extra + (size_t)row * DD + c);
                    v0 += rr.x; v1 += rr.y;
                }
                if (Ch) *(__half2*)(Ch + (size_t)row * DD + c) = __floats2half2_rn(v0, v1);
                else    *(float2*)(Cf + (size_t)row * DD + c) = make_float2(v0, v1);
            }
        }
    }
}

// ------------- fused bind + intra-chunk cumsum + retrieve + layernorm ----------
__global__ void __launch_bounds__(512)
scan_ln(const __half* __restrict__ val, const float* __restrict__ kp,
        const float* __restrict__ qp, const float* __restrict__ lng,
        const float* __restrict__ lnb, __half* __restrict__ oh)
{
    __shared__ float rs[16], rs2[16];
    __shared__ float s_mu, s_rstd;

    const int d    = threadIdx.x;
    const int lane = d & 31;
    const int wid  = d >> 5;
    const size_t base = (size_t)blockIdx.x * CHUNK * DD + d;
    const float g0 = lng[d],       b0 = lnb[d];
    const float g1 = lng[d + 512], b1 = lnb[d + 512];

    __half cv0 = val[base],  cv1 = val[base + 512];
    float  cpk0 = kp[base],  cpk1 = kp[base + 512];
    float  cpq0 = qp[base],  cpq1 = qp[base + 512];

    float ar0 = 0.f, ai0 = 0.f, ar1 = 0.f, ai1 = 0.f;
#pragma unroll 1
    for (int r = 0; r < CHUNK; r++) {
        __half nv0, nv1; float npk0, npk1, npq0, npq1;
        if (r + 1 < CHUNK) {
            const size_t nx = base + (size_t)(r + 1) * DD;
            nv0 = val[nx];  nv1 = val[nx + 512];
            npk0 = kp[nx];  npk1 = kp[nx + 512];
            npq0 = qp[nx];  npq1 = qp[nx + 512];
        }

        const float v0 = __half2float(cv0), v1 = __half2float(cv1);
        float sk0, ck0, sq0, cq0, sk1, ck1, sq1, cq1;
        __sincosf(cpk0, &sk0, &ck0);
        __sincosf(cpq0, &sq0, &cq0);
        __sincosf(cpk1, &sk1, &ck1);
        __sincosf(cpq1, &sq1, &cq1);
        ar0 = fmaf(v0, ck0, ar0);  ai0 = fmaf(v0, sk0, ai0);
        ar1 = fmaf(v1, ck1, ar1);  ai1 = fmaf(v1, sk1, ai1);
        const float x0 = (ar0 * cq0 + ai0 * sq0) * 0.03125f;
        const float x1 = (ar1 * cq1 + ai1 * sq1) * 0.03125f;

        float s = x0 + x1, s2 = x0 * x0 + x1 * x1;
#pragma unroll
        for (int o = 16; o; o >>= 1) {
            s  += __shfl_xor_sync(0xffffffffu, s,  o);
            s2 += __shfl_xor_sync(0xffffffffu, s2, o);
        }
        if (lane == 0) { rs[wid] = s; rs2[wid] = s2; }
        __syncthreads();
        if (wid == 0) {
            s  = (lane < 16) ? rs[lane]  : 0.f;
            s2 = (lane < 16) ? rs2[lane] : 0.f;
#pragma unroll
            for (int o = 8; o; o >>= 1) {
                s  += __shfl_xor_sync(0xffffffffu, s,  o);
                s2 += __shfl_xor_sync(0xffffffffu, s2, o);
            }
            if (lane == 0) {
                const float mu  = s * (1.f / DD);
                const float var = s2 * (1.f / DD) - mu * mu;
                s_mu   = mu;
                s_rstd = rsqrtf(var + 1e-5f);
            }
        }
        __syncthreads();
        const size_t idx = base + (size_t)r * DD;
        oh[idx]       = __float2half_rn((x0 - s_mu) * s_rstd * g0 + b0);
        oh[idx + 512] = __float2half_rn((x1 - s_mu) * s_rstd * g1 + b1);

        cv0 = nv0; cv1 = nv1;
        cpk0 = npk0; cpk1 = npk1;
        cpq0 = npq0; cpq1 = npq1;
    }
}

// --------------------------------- launch --------------------------------------
extern "C" void kernel_launch(void* const* d_in, const int* in_sizes, int n_in,
                              void* d_out, int out_size)
{
    const float* x   = (const float*)d_in[0];
    const float* Wk  = (const float*)d_in[1];
    const float* bk  = (const float*)d_in[2];
    const float* Wv  = (const float*)d_in[3];
    const float* bv  = (const float*)d_in[4];
    const float* Wq  = (const float*)d_in[5];
    const float* bq  = (const float*)d_in[6];
    const float* Wkp = (const float*)d_in[7];
    const float* bkp = (const float*)d_in[8];
    const float* Wqp = (const float*)d_in[9];
    const float* bqp = (const float*)d_in[10];
    const float* ps  = (const float*)d_in[11];
    const float* lng = (const float*)d_in[12];
    const float* lnb = (const float*)d_in[13];
    const float* Wo  = (const float*)d_in[14];
    const float* bo  = (const float*)d_in[15];
    float* out = (float*)d_out;

    __half *xh, *lnh, *valh;
    __half *wv_h, *wo_h, *wkp_h, *wkp_l, *wqp_h, *wqp_l;
    __half *wkt_h, *wqt_h, *wck_h, *wcq_h;
    float *kpv, *qpv, *bck, *bcq;
    cudaGetSymbolAddress((void**)&xh,    g_xh);
    cudaGetSymbolAddress((void**)&lnh,   g_lnh);
    cudaGetSymbolAddress((void**)&valh,  g_valh);
    cudaGetSymbolAddress((void**)&kpv,   g_kp);
    cudaGetSymbolAddress((void**)&qpv,   g_qp);
    cudaGetSymbolAddress((void**)&wv_h,  g_wv_h);
    cudaGetSymbolAddress((void**)&wo_h,  g_wo_h);
    cudaGetSymbolAddress((void**)&wkp_h, g_wkp_h);
    cudaGetSymbolAddress((void**)&wkp_l, g_wkp_l);
    cudaGetSymbolAddress((void**)&wqp_h, g_wqp_h);
    cudaGetSymbolAddress((void**)&wqp_l, g_wqp_l);
    cudaGetSymbolAddress((void**)&wkt_h, g_wkt_h);
    cudaGetSymbolAddress((void**)&wqt_h, g_wqt_h);
    cudaGetSymbolAddress((void**)&wck_h, g_wck_h);
    cudaGetSymbolAddress((void**)&wcq_h, g_wcq_h);
    cudaGetSymbolAddress((void**)&bck,   g_bck);
    cudaGetSymbolAddress((void**)&bcq,   g_bcq);

    cudaFuncSetAttribute(gemm1p, cudaFuncAttributeMaxDynamicSharedMemorySize, SMEM_BYTES);
    cudaFuncSetAttribute(gemm2w, cudaFuncAttributeMaxDynamicSharedMemorySize, SMEM2W_BYTES);

    static cudaStream_t s_pre = nullptr;
    static cudaEvent_t ev_fork = nullptr, ev_wsplit = nullptr, ev_comb = nullptr;
    if (s_pre == nullptr) {
        cudaStreamCreateWithFlags(&s_pre, cudaStreamNonBlocking);
        cudaEventCreateWithFlags(&ev_fork,   cudaEventDisableTiming);
        cudaEventCreateWithFlags(&ev_wsplit, cudaEventDisableTiming);
        cudaEventCreateWithFlags(&ev_comb,   cudaEventDisableTiming);
    }

    // ---- fork ----
    cudaEventRecord(ev_fork, 0);
    cudaStreamWaitEvent(s_pre, ev_fork, 0);

    // s_pre: weight split (produces wv_h needed by val GEMM) -> ev_wsplit
    split3<<<dim3(DD * DD / 1024, 3), 256, 0, s_pre>>>(Wv, Wkp, Wqp,
        wv_h, nullptr, wkp_h, wkp_l, wqp_h, wqp_l);
    cudaEventRecord(ev_wsplit, s_pre);
    // s_pre continues: combine chain -> ev_comb
    tsplit<<<dim3(32, 32, 2), 256, 0, s_pre>>>(Wk, Wq, wkt_h, wqt_h);
    matvec<<<dim3(DD, 2), 256, 0, s_pre>>>(Wkp, bk, bkp, Wqp, bq, bqp, bck, bcq);
    {
        CombArgs a = {};
        a.Ah[0] = wkp_h; a.Al[0] = wkp_l; a.Wh[0] = wkt_h; a.Ch[0] = wck_h;
        a.Ah[1] = wqp_h; a.Al[1] = wqp_l; a.Wh[1] = wqt_h; a.Ch[1] = wcq_h;
        gemm2w<<<dim3(DD / 128, DD / 128, 2), 256, SMEM2W_BYTES, s_pre>>>(a);
    }
    cudaEventRecord(ev_comb, s_pre);

    // default stream: x split + Wo split
    split3<<<dim3(MB * DD / 1024, 1), 256>>>(x, x, x,
        xh, nullptr, nullptr, nullptr, nullptr, nullptr);
    split3<<<dim3(DD * DD / 1024, 1), 256>>>(Wo, Wo, Wo,
        wo_h, nullptr, nullptr, nullptr, nullptr, nullptr);

    // val GEMM needs only xh + wv_h
    cudaStreamWaitEvent(0, ev_wsplit, 0);
    {
        GemmArgs a = {};
        a.Ah[0] = xh; a.Wh[0] = wv_h; a.bias[0] = bv; a.mode[0] = 0; a.Ch[0] = valh;
        a.nz = 1;
        gemm1p<<<dim3(DD / BN, MB / BM), 256, SMEM_BYTES>>>(a);
    }
    // kp/qp GEMM needs the combined weights.
    cudaStreamWaitEvent(0, ev_comb, 0);
    {
        GemmArgs a = {};
        a.Ah[0] = a.Ah[1] = xh;
        a.Wh[0] = wck_h; a.bias[0] = bck; a.mode[0] = 1; a.Cf[0] = kpv; a.extra[0] = ps;
        a.Wh[1] = wcq_h; a.bias[1] = bcq; a.mode[1] = 1; a.Cf[1] = qpv; a.extra[1] = ps;
        a.nz = 2;
        gemm1p<<<dim3(2 * DD / BN, MB / BM), 256, SMEM_BYTES>>>(a);
    }
    // bind + chunked cumsum + retrieve + layernorm -> hi fp16
    scan_ln<<<MB / CHUNK, 512>>>(valh, kpv, qpv, lng, lnb, lnh);
    // output projection + residual
    {
        GemmArgs a = {};
        a.Ah[0] = lnh; a.Wh[0] = wo_h; a.bias[0] = bo;
        a.mode[0] = 2; a.extra[0] = x; a.Cf[0] = out;
        a.nz = 1;
        gemm1p<<<dim3(DD / BN, MB / BM), 256, SMEM_BYTES>>>(a);
    }
}

// round 17
// speedup vs baseline: 1.0191x; 1.0191x over previous
#include <cuda_runtime.h>
#include <cuda_fp16.h>
#include <math.h>
#include <stdint.h>

#define DD    1024
#define MB    16384
#define CHUNK 64
// gemm1p tile: CTA 128x128, 8 warps of 32x64 (R8 config: proven optimum)
#define BM    128
#define BN    128
#define BK    64
#define NKC   (DD / BK)        // 16
#define STAGE_B 32768u         // Ah 16K | Wh 16K
#define NSTG  3
#define SMEM_BYTES (NSTG * STAGE_B)
// gemm2w (combine, 2-pass) tile: 64x128 -> 256 CTAs (fills the machine)
#define STAGE2W_B 32768u       // Ah 8K | Al 8K | Wh 16K
#define SMEM2W_BYTES (2u * STAGE2W_B)

// ---------------- scratch (static device arrays; no allocation) ----------------
__device__ __half g_xh[MB * DD];
__device__ __half g_lnh[MB * DD];
__device__ __half g_valh[MB * DD];
__device__ float  g_kp [MB * DD], g_qp[MB * DD];
__device__ __half g_wv_h[DD * DD], g_wo_h[DD * DD];
__device__ __half g_wkp_h[DD * DD], g_wkp_l[DD * DD];
__device__ __half g_wqp_h[DD * DD], g_wqp_l[DD * DD];
__device__ __half g_wkt_h[DD * DD];
__device__ __half g_wqt_h[DD * DD];
__device__ __half g_wck_h[DD * DD], g_wcq_h[DD * DD];
__device__ float  g_bck[DD], g_bcq[DD];

// ---------------- helpers ----------------
__device__ __forceinline__ uint32_t smem_u32(const void* p) {
    uint32_t a;
    asm("{ .reg .u64 t; cvta.to.shared.u64 t, %1; cvt.u32.u64 %0, t; }" : "=r"(a) : "l"(p));
    return a;
}
__device__ __forceinline__ void cp_async16(uint32_t dst, const void* src) {
    asm volatile("cp.async.cg.shared.global [%0], [%1], 16;" :: "r"(dst), "l"(src));
}
__device__ __forceinline__ void cp_commit() {
    asm volatile("cp.async.commit_group;" ::: "memory");
}
template<int N>
__device__ __forceinline__ void cp_wait() {
    asm volatile("cp.async.wait_group %0;" :: "n"(N) : "memory");
}
__device__ __forceinline__ void ldsm4(uint32_t* r, uint32_t addr) {
    asm volatile("ldmatrix.sync.aligned.m8n8.x4.shared.b16 {%0,%1,%2,%3}, [%4];"
                 : "=r"(r[0]), "=r"(r[1]), "=r"(r[2]), "=r"(r[3]) : "r"(addr));
}
__device__ __forceinline__ void mma16816(float* c, const uint32_t* a, uint32_t b0, uint32_t b1) {
    asm volatile(
        "mma.sync.aligned.m16n8k16.row.col.f32.f16.f16.f32 "
        "{%0,%1,%2,%3}, {%4,%5,%6,%7}, {%8,%9}, {%0,%1,%2,%3};"
        : "+f"(c[0]), "+f"(c[1]), "+f"(c[2]), "+f"(c[3])
        : "r"(a[0]), "r"(a[1]), "r"(a[2]), "r"(a[3]), "r"(b0), "r"(b1));
}
__device__ __forceinline__ void split2(float v0, float v1, uint32_t& h, uint32_t& l) {
    __half2 hh = __floats2half2_rn(v0, v1);
    float2 f = __half22float2(hh);
    __half2 ll = __floats2half2_rn(v0 - f.x, v1 - f.y);
    h = *(uint32_t*)&hh; l = *(uint32_t*)&ll;
}

// ---------------- fp32 -> (hi fp16 [, lo fp16]) split, 3 matrices per launch ---
__global__ void __launch_bounds__(256)
split3(const float* __restrict__ s0, const float* __restrict__ s1, const float* __restrict__ s2,
       __half* h0, __half* l0, __half* h1, __half* l1, __half* h2, __half* l2)
{
    const int z = blockIdx.y;
    const float* s = (z == 0) ? s0 : (z == 1) ? s1 : s2;
    __half* h = (z == 0) ? h0 : (z == 1) ? h1 : h2;
    __half* l = (z == 0) ? l0 : (z == 1) ? l1 : l2;
    const size_t i = ((size_t)blockIdx.x * 256 + threadIdx.x) * 4;
    const float4 v = *(const float4*)(s + i);
    uint32_t ha, la, hb, lb;
    split2(v.x, v.y, ha, la);
    split2(v.z, v.w, hb, lb);
    *(uint2*)(h + i) = make_uint2(ha, hb);
    if (l) *(uint2*)(l + i) = make_uint2(la, lb);
}

// ---------------- transpose (hi fp16 only): out[d][m] = in[m][d] ---------------
__global__ void __launch_bounds__(256)
tsplit(const float* __restrict__ s0, const float* __restrict__ s1,
       __half* h0, __half* h1)
{
    __shared__ float t[32][33];
    const int z = blockIdx.z;
    const float* s = z ? s1 : s0;
    __half* h = z ? h1 : h0;
    const int bx = blockIdx.x * 32, by = blockIdx.y * 32;
    const int tx = threadIdx.x & 31, ty = threadIdx.x >> 5;
#pragma unroll
    for (int i = 0; i < 32; i += 8)
        t[ty + i][tx] = s[(size_t)(by + ty + i) * DD + bx + tx];
    __syncthreads();
#pragma unroll
    for (int i = 0; i < 32; i += 8) {
        const float v = t[tx][ty + i];
        h[(size_t)(bx + ty + i) * DD + by + tx] = __float2half_rn(v);
    }
}

// ---------------- bias combine: o[e] = a[e] + sum_m W[e,m] * v[m] --------------
__global__ void __launch_bounds__(256)
matvec(const float* __restrict__ W0, const float* __restrict__ v0, const float* __restrict__ a0,
       const float* __restrict__ W1, const float* __restrict__ v1, const float* __restrict__ a1,
       float* o0, float* o1)
{
    const int z = blockIdx.y;
    const float* W = z ? W1 : W0;
    const float* v = z ? v1 : v0;
    const float* a = z ? a1 : a0;
    float* o = z ? o1 : o0;
    const int e = blockIdx.x, t = threadIdx.x;
    float s = 0.f;
    for (int m = t; m < DD; m += 256)
        s += W[(size_t)e * DD + m] * v[m];
    __shared__ float r[8];
#pragma unroll
    for (int off = 16; off; off >>= 1) s += __shfl_xor_sync(0xffffffffu, s, off);
    if ((t & 31) == 0) r[t >> 5] = s;
    __syncthreads();
    if (t == 0) {
        float tot = a[e];
#pragma unroll
        for (int w = 0; w < 8; w++) tot += r[w];
        o[e] = tot;
    }
}

// ------- 2-pass combine GEMM: Wc[64,128] tile = (Ah+Al) @ Wh^T -> hi fp16 ------
// 256 CTAs (fills all SMs), warp tile 32x32, 8 warps 2x4.
struct CombArgs {
    const __half* Ah[2]; const __half* Al[2];
    const __half* Wh[2];
    __half* Ch[2];
};
__global__ void __launch_bounds__(256, 2)
gemm2w(CombArgs ga)
{
    extern __shared__ char smem[];
    const int tid = threadIdx.x;
    const int z = blockIdx.z;
    const __half* Ahg = ga.Ah[z];
    const __half* Alg = ga.Al[z];
    const __half* Whg = ga.Wh[z];

    const int bm = blockIdx.y * 64;
    const int bn = blockIdx.x * 128;
    const uint32_t sbu = smem_u32(smem);

    auto issue = [&](int kt, int s) {
        const uint32_t st = sbu + (uint32_t)s * STAGE2W_B;
        const int kof = kt * BK;
#pragma unroll
        for (int i = 0; i < 2; i++) {                // Ah + Al: 512 chunks each
            const int idx = tid + (i << 8);
            const int row = idx >> 3, c = idx & 7;
            const uint32_t so = st + (uint32_t)row * 128u
                              + (((uint32_t)c * 16u) ^ (((uint32_t)row & 7u) << 4));
            const size_t gA = (size_t)(bm + row) * DD + kof + c * 8;
            cp_async16(so,         Ahg + gA);
            cp_async16(so + 8192u, Alg + gA);
        }
#pragma unroll
        for (int i = 0; i < 4; i++) {                // Wh: 1024 chunks
            const int idx = tid + (i << 8);
            const int row = idx >> 3, c = idx & 7;
            const uint32_t so = st + 16384u + (uint32_t)row * 128u
                              + (((uint32_t)c * 16u) ^ (((uint32_t)row & 7u) << 4));
            cp_async16(so, Whg + (size_t)(bn + row) * DD + kof + c * 8);
        }
    };

    const int warp = tid >> 5, lane = tid & 31;
    const int wm0 = (warp >> 2) * 32;   // 0 / 32
    const int wn0 = (warp & 3) * 32;    // 0..96
    const int lr = lane & 15;
    const uint32_t lc   = ((uint32_t)lane >> 4) * 16u;
    const uint32_t xorv = ((uint32_t)lane & 7u) << 4;

    float acc[2][4][4];
#pragma unroll
    for (int mi = 0; mi < 2; mi++)
#pragma unroll
        for (int ni = 0; ni < 4; ni++)
#pragma unroll
            for (int q = 0; q < 4; q++) acc[mi][ni][q] = 0.f;

    auto compute = [&](int s) {
        const uint32_t sA = sbu + (uint32_t)s * STAGE2W_B;
        const uint32_t sW = sA + 16384u;
#pragma unroll
        for (int kk = 0; kk < 4; kk++) {
            const uint32_t koff = (((uint32_t)kk * 32u) + lc) ^ xorv;
            uint32_t ah[2][4], al[2][4], wh[2][4];
#pragma unroll
            for (int mi = 0; mi < 2; mi++) {
                const uint32_t rb = (uint32_t)((wm0 + mi * 16 + lr) * 128) + koff;
                ldsm4(ah[mi], sA + rb);
                ldsm4(al[mi], sA + 8192u + rb);
            }
#pragma unroll
            for (int g = 0; g < 2; g++)
                ldsm4(wh[g], sW + (uint32_t)((wn0 + g * 16 + lr) * 128) + koff);
#pragma unroll
            for (int mi = 0; mi < 2; mi++)
#pragma unroll
                for (int ni = 0; ni < 4; ni++) {
                    const uint32_t* b = wh[ni >> 1];
                    mma16816(acc[mi][ni], ah[mi], b[ni & 1], b[(ni & 1) + 2]);
                }
#pragma unroll
            for (int mi = 0; mi < 2; mi++)
#pragma unroll
                for (int ni = 0; ni < 4; ni++) {
                    const uint32_t* b = wh[ni >> 1];
                    mma16816(acc[mi][ni], al[mi], b[ni & 1], b[(ni & 1) + 2]);
                }
        }
    };

    issue(0, 0); cp_commit();
    issue(1, 1); cp_commit();
    cp_wait<1>();
    __syncthreads();
#pragma unroll 1
    for (int kt = 0; kt < NKC; kt++) {
        compute(kt & 1);
        __syncthreads();
        if (kt + 2 < NKC) issue(kt + 2, kt & 1);
        cp_commit();
        cp_wait<1>();
        __syncthreads();
    }

    __half* Ch = ga.Ch[z];
#pragma unroll
    for (int ni = 0; ni < 4; ni++) {
        const int c = bn + wn0 + ni * 8 + (lane & 3) * 2;
#pragma unroll
        for (int mi = 0; mi < 2; mi++) {
#pragma unroll
            for (int hf = 0; hf < 2; hf++) {
                const int row = bm + wm0 + mi * 16 + (lane >> 2) + hf * 8;
                __half2 hv = __floats2half2_rn(acc[mi][ni][hf * 2], acc[mi][ni][hf * 2 + 1]);
                *(__half2*)(Ch + (size_t)row * DD + c) = hv;
            }
        }
    }
}

// ---------------- GEMM args (runtime per-slice epilogue mode) ------------------
struct GemmArgs {
    const __half* Ah[3];
    const __half* Wh[3];
    const float*  bias[3];
    const float*  extra[3];         // mode1: phase_scale ; mode2: residual x
    float*  Cf[3];                  // fp32 output (or null)
    __half* Ch[3];                  // fp16 output (or null)
    int mode[3];
    int nz;                         // number of z slices folded into grid.x
};

// ------- 1-pass mma GEMM (R8 config): C[128,128], 8 warps 32x64, 3-stage -------
__global__ void __launch_bounds__(256, 2)
gemm1p(GemmArgs ga)
{
    extern __shared__ char smem[];
    const int tid = threadIdx.x;
    const int z  = blockIdx.x % ga.nz;
    const int bn = (blockIdx.x / ga.nz) * BN;
    const __half* Ahg = ga.Ah[z];
    const __half* Whg = ga.Wh[z];
    const float*  bias = ga.bias[z];

    const int bm = blockIdx.y * BM;
    const uint32_t sbu = smem_u32(smem);

    auto issue = [&](int kt, int s) {
        const uint32_t st = sbu + (uint32_t)s * STAGE_B;
        const int kof = kt * BK;
#pragma unroll
        for (int i = 0; i < 4; i++) {
            const int idx = tid + (i << 8);
            const int row = idx >> 3, c = idx & 7;
            const uint32_t so = st + (uint32_t)row * 128u
                              + (((uint32_t)c * 16u) ^ (((uint32_t)row & 7u) << 4));
            cp_async16(so,          Ahg + (size_t)(bm + row) * DD + kof + c * 8);
            cp_async16(so + 16384u, Whg + (size_t)(bn + row) * DD + kof + c * 8);
        }
    };

    const int warp = tid >> 5, lane = tid & 31;
    const int wm0 = (warp >> 1) * 32;
    const int wn0 = (warp & 1) * 64;
    const int lr = lane & 15;
    const uint32_t lc   = ((uint32_t)lane >> 4) * 16u;
    const uint32_t xorv = ((uint32_t)lane & 7u) << 4;

    float acc[2][8][4];
#pragma unroll
    for (int mi = 0; mi < 2; mi++)
#pragma unroll
        for (int ni = 0; ni < 8; ni++)
#pragma unroll
            for (int q = 0; q < 4; q++) acc[mi][ni][q] = 0.f;

    auto compute = [&](int s) {
        const uint32_t sA = sbu + (uint32_t)s * STAGE_B;
        const uint32_t sW = sA + 16384u;
#pragma unroll
        for (int kk = 0; kk < 4; kk++) {
            const uint32_t koff = (((uint32_t)kk * 32u) + lc) ^ xorv;
            uint32_t ah[2][4], wh[4][4];
#pragma unroll
            for (int mi = 0; mi < 2; mi++)
                ldsm4(ah[mi], sA + (uint32_t)((wm0 + mi * 16 + lr) * 128) + koff);
#pragma unroll
            for (int g = 0; g < 4; g++)
                ldsm4(wh[g], sW + (uint32_t)((wn0 + g * 16 + lr) * 128) + koff);
#pragma unroll
            for (int mi = 0; mi < 2; mi++)
#pragma unroll
                for (int ni = 0; ni < 8; ni++) {
                    const uint32_t* b = wh[ni >> 1];
                    mma16816(acc[mi][ni], ah[mi], b[ni & 1], b[(ni & 1) + 2]);
                }
        }
    };

    issue(0, 0); cp_commit();
    issue(1, 1); cp_commit();
#pragma unroll 1
    for (int kt = 0; kt < NKC; kt++) {
        cp_wait<1>();
        __syncthreads();
        if (kt + 2 < NKC) issue(kt + 2, (kt + 2) % NSTG);
        cp_commit();
        compute(kt % NSTG);
    }

    // ---- epilogue ----
    const int mode = ga.mode[z];
    const float* extra = ga.extra[z];
    float*  Cf = ga.Cf[z];
    __half* Ch = ga.Ch[z];

#pragma unroll
    for (int ni = 0; ni < 8; ni++) {
        const int c = bn + wn0 + ni * 8 + (lane & 3) * 2;
        const float b0 = bias[c], b1 = bias[c + 1];
        float p0 = 0.f, p1 = 0.f;
        if (mode == 1) { p0 = extra[c]; p1 = extra[c + 1]; }
#pragma unroll
        for (int mi = 0; mi < 2; mi++) {
#pragma unroll
            for (int hf = 0; hf < 2; hf++) {
                const int row = bm + wm0 + mi * 16 + (lane >> 2) + hf * 8;
                float v0 = acc[mi][ni][hf * 2 + 0] + b0;
                float v1 = acc[mi][ni][hf * 2 + 1] + b1;
                if (mode == 1) { v0 = tanhf(v0) * p0; v1 = tanhf(v1) * p1; }
                if (mode == 2) {
                    const float2 rr = *(const float2*)(extra + (size_t)row * DD + c);
                    v0 += rr.x; v1 += rr.y;
                }
                if (Ch) *(__half2*)(Ch + (size_t)row * DD + c) = __floats2half2_rn(v0, v1);
                else    *(float2*)(Cf + (size_t)row * DD + c) = make_float2(v0, v1);
            }
        }
    }
}

// ------------- fused bind + intra-chunk cumsum + retrieve + layernorm ----------
__global__ void __launch_bounds__(512)
scan_ln(const __half* __restrict__ val, const float* __restrict__ kp,
        const float* __restrict__ qp, const float* __restrict__ lng,
        const float* __restrict__ lnb, __half* __restrict__ oh)
{
    __shared__ float rs[16], rs2[16];
    __shared__ float s_mu, s_rstd;

    const int d    = threadIdx.x;
    const int lane = d & 31;
    const int wid  = d >> 5;
    const size_t base = (size_t)blockIdx.x * CHUNK * DD + d;
    const float g0 = lng[d],       b0 = lnb[d];
    const float g1 = lng[d + 512], b1 = lnb[d + 512];

    __half cv0 = val[base],  cv1 = val[base + 512];
    float  cpk0 = kp[base],  cpk1 = kp[base + 512];
    float  cpq0 = qp[base],  cpq1 = qp[base + 512];

    float ar0 = 0.f, ai0 = 0.f, ar1 = 0.f, ai1 = 0.f;
#pragma unroll 1
    for (int r = 0; r < CHUNK; r++) {
        __half nv0, nv1; float npk0, npk1, npq0, npq1;
        if (r + 1 < CHUNK) {
            const size_t nx = base + (size_t)(r + 1) * DD;
            nv0 = val[nx];  nv1 = val[nx + 512];
            npk0 = kp[nx];  npk1 = kp[nx + 512];
            npq0 = qp[nx];  npq1 = qp[nx + 512];
        }

        const float v0 = __half2float(cv0), v1 = __half2float(cv1);
        float sk0, ck0, sq0, cq0, sk1, ck1, sq1, cq1;
        __sincosf(cpk0, &sk0, &ck0);
        __sincosf(cpq0, &sq0, &cq0);
        __sincosf(cpk1, &sk1, &ck1);
        __sincosf(cpq1, &sq1, &cq1);
        ar0 = fmaf(v0, ck0, ar0);  ai0 = fmaf(v0, sk0, ai0);
        ar1 = fmaf(v1, ck1, ar1);  ai1 = fmaf(v1, sk1, ai1);
        const float x0 = (ar0 * cq0 + ai0 * sq0) * 0.03125f;
        const float x1 = (ar1 * cq1 + ai1 * sq1) * 0.03125f;

        float s = x0 + x1, s2 = x0 * x0 + x1 * x1;
#pragma unroll
        for (int o = 16; o; o >>= 1) {
            s  += __shfl_xor_sync(0xffffffffu, s,  o);
            s2 += __shfl_xor_sync(0xffffffffu, s2, o);
        }
        if (lane == 0) { rs[wid] = s; rs2[wid] = s2; }
        __syncthreads();
        if (wid == 0) {
            s  = (lane < 16) ? rs[lane]  : 0.f;
            s2 = (lane < 16) ? rs2[lane] : 0.f;
#pragma unroll
            for (int o = 8; o; o >>= 1) {
                s  += __shfl_xor_sync(0xffffffffu, s,  o);
                s2 += __shfl_xor_sync(0xffffffffu, s2, o);
            }
            if (lane == 0) {
                const float mu  = s * (1.f / DD);
                const float var = s2 * (1.f / DD) - mu * mu;
                s_mu   = mu;
                s_rstd = rsqrtf(var + 1e-5f);
            }
        }
        __syncthreads();
        const size_t idx = base + (size_t)r * DD;
        oh[idx]       = __float2half_rn((x0 - s_mu) * s_rstd * g0 + b0);
        oh[idx + 512] = __float2half_rn((x1 - s_mu) * s_rstd * g1 + b1);

        cv0 = nv0; cv1 = nv1;
        cpk0 = npk0; cpk1 = npk1;
        cpq0 = npq0; cpq1 = npq1;
    }
}

// --------------------------------- launch --------------------------------------
extern "C" void kernel_launch(void* const* d_in, const int* in_sizes, int n_in,
                              void* d_out, int out_size)
{
    const float* x   = (const float*)d_in[0];
    const float* Wk  = (const float*)d_in[1];
    const float* bk  = (const float*)d_in[2];
    const float* Wv  = (const float*)d_in[3];
    const float* bv  = (const float*)d_in[4];
    const float* Wq  = (const float*)d_in[5];
    const float* bq  = (const float*)d_in[6];
    const float* Wkp = (const float*)d_in[7];
    const float* bkp = (const float*)d_in[8];
    const float* Wqp = (const float*)d_in[9];
    const float* bqp = (const float*)d_in[10];
    const float* ps  = (const float*)d_in[11];
    const float* lng = (const float*)d_in[12];
    const float* lnb = (const float*)d_in[13];
    const float* Wo  = (const float*)d_in[14];
    const float* bo  = (const float*)d_in[15];
    float* out = (float*)d_out;

    __half *xh, *lnh, *valh;
    __half *wv_h, *wo_h, *wkp_h, *wkp_l, *wqp_h, *wqp_l;
    __half *wkt_h, *wqt_h, *wck_h, *wcq_h;
    float *kpv, *qpv, *bck, *bcq;
    cudaGetSymbolAddress((void**)&xh,    g_xh);
    cudaGetSymbolAddress((void**)&lnh,   g_lnh);
    cudaGetSymbolAddress((void**)&valh,  g_valh);
    cudaGetSymbolAddress((void**)&kpv,   g_kp);
    cudaGetSymbolAddress((void**)&qpv,   g_qp);
    cudaGetSymbolAddress((void**)&wv_h,  g_wv_h);
    cudaGetSymbolAddress((void**)&wo_h,  g_wo_h);
    cudaGetSymbolAddress((void**)&wkp_h, g_wkp_h);
    cudaGetSymbolAddress((void**)&wkp_l, g_wkp_l);
    cudaGetSymbolAddress((void**)&wqp_h, g_wqp_h);
    cudaGetSymbolAddress((void**)&wqp_l, g_wqp_l);
    cudaGetSymbolAddress((void**)&wkt_h, g_wkt_h);
    cudaGetSymbolAddress((void**)&wqt_h, g_wqt_h);
    cudaGetSymbolAddress((void**)&wck_h, g_wck_h);
    cudaGetSymbolAddress((void**)&wcq_h, g_wcq_h);
    cudaGetSymbolAddress((void**)&bck,   g_bck);
    cudaGetSymbolAddress((void**)&bcq,   g_bcq);

    cudaFuncSetAttribute(gemm1p, cudaFuncAttributeMaxDynamicSharedMemorySize, SMEM_BYTES);
    cudaFuncSetAttribute(gemm2w, cudaFuncAttributeMaxDynamicSharedMemorySize, SMEM2W_BYTES);

    static cudaStream_t s_pre = nullptr;
    static cudaEvent_t ev_fork = nullptr, ev_comb = nullptr;
    if (s_pre == nullptr) {
        cudaStreamCreateWithFlags(&s_pre, cudaStreamNonBlocking);
        cudaEventCreateWithFlags(&ev_fork, cudaEventDisableTiming);
        cudaEventCreateWithFlags(&ev_comb, cudaEventDisableTiming);
    }

    // ---- fork: combine chain on s_pre, splits on default stream ----
    cudaEventRecord(ev_fork, 0);
    cudaStreamWaitEvent(s_pre, ev_fork, 0);

    split3<<<dim3(DD * DD / 1024, 3), 256, 0, s_pre>>>(Wv, Wkp, Wqp,
        wv_h, nullptr, wkp_h, wkp_l, wqp_h, wqp_l);
    tsplit<<<dim3(32, 32, 2), 256, 0, s_pre>>>(Wk, Wq, wkt_h, wqt_h);
    matvec<<<dim3(DD, 2), 256, 0, s_pre>>>(Wkp, bk, bkp, Wqp, bq, bqp, bck, bcq);
    {
        CombArgs a = {};
        a.Ah[0] = wkp_h; a.Al[0] = wkp_l; a.Wh[0] = wkt_h; a.Ch[0] = wck_h;
        a.Ah[1] = wqp_h; a.Al[1] = wqp_l; a.Wh[1] = wqt_h; a.Ch[1] = wcq_h;
        gemm2w<<<dim3(DD / 128, DD / 64, 2), 256, SMEM2W_BYTES, s_pre>>>(a);
    }
    cudaEventRecord(ev_comb, s_pre);

    // default stream: x split + Wo split
    split3<<<dim3(MB * DD / 1024, 1), 256>>>(x, x, x,
        xh, nullptr, nullptr, nullptr, nullptr, nullptr);
    split3<<<dim3(DD * DD / 1024, 1), 256>>>(Wo, Wo, Wo,
        wo_h, nullptr, nullptr, nullptr, nullptr, nullptr);

    // ---- join (R13 schedule: single z=3 GEMM with grid-x fold) ----
    cudaStreamWaitEvent(0, ev_comb, 0);
    {
        GemmArgs a = {};
        a.Ah[0] = a.Ah[1] = a.Ah[2] = xh;
        a.Wh[0] = wv_h;  a.bias[0] = bv;  a.mode[0] = 0; a.Ch[0] = valh;
        a.Wh[1] = wck_h; a.bias[1] = bck; a.mode[1] = 1; a.Cf[1] = kpv; a.extra[1] = ps;
        a.Wh[2] = wcq_h; a.bias[2] = bcq; a.mode[2] = 1; a.Cf[2] = qpv; a.extra[2] = ps;
        a.nz = 3;
        gemm1p<<<dim3(3 * DD / BN, MB / BM), 256, SMEM_BYTES>>>(a);
    }
    // bind + chunked cumsum + retrieve + layernorm -> hi fp16
    scan_ln<<<MB / CHUNK, 512>>>(valh, kpv, qpv, lng, lnb, lnh);
    // output projection + residual
    {
        GemmArgs a = {};
        a.Ah[0] = lnh; a.Wh[0] = wo_h; a.bias[0] = bo;
        a.mode[0] = 2; a.extra[0] = x; a.Cf[0] = out;
        a.nz = 1;
        gemm1p<<<dim3(DD / BN, MB / BM), 256, SMEM_BYTES>>>(a);
    }
}